// round 3
// baseline (speedup 1.0000x reference)
#include <cuda_runtime.h>
#include <cuda_bf16.h>
#include <cstdint>

#define N_MAX   100000
#define E_MAX   1600000
#define HID     64
#define IN_DIM  128

// ---------------- scratch (device globals; no allocation allowed) ----------
__device__ float g_h[N_MAX * HID];       // MLP output features
__device__ float g_rnorm[N_MAX];         // 1 / max(||h||, 1e-12)
__device__ int   g_src[E_MAX];
__device__ int   g_dst[E_MAX];
__device__ int   g_rank[E_MAX];
__device__ int   g_deg[N_MAX];
__device__ int   g_incl[N_MAX];
__device__ int   g_rs[N_MAX];
__device__ int   g_re[N_MAX];
__device__ int   g_csr[E_MAX];
__device__ int   g_bsum[1024];
__device__ int   g_boff[1024];
__device__ int   g_is64;
// prepped weight smem image: [w1h | w1l | w2h | w2l] packed-u32 bf16 pairs
// w1 tiles: 64 rows(n) x 68 u32 (k-pairs, stride 136 halves = 272B)
// w2 tiles: 64 rows(n) x 36 u32 (stride 72 halves = 144B)
#define W1_U32  (64 * 68)    // 4352
#define W2_U32  (64 * 36)    // 2304
#define WIMG_U32 (2 * W1_U32 + 2 * W2_U32)   // 13312 u32 = 53248 B
__device__ __align__(16) uint32_t g_wimg[WIMG_U32];

// ---------------- helpers ---------------------------------------------------
__device__ __forceinline__ void split2(float v0, float v1, uint32_t& hi, uint32_t& lo) {
    __nv_bfloat16 h0 = __float2bfloat16(v0);
    __nv_bfloat16 h1 = __float2bfloat16(v1);
    float r0 = v0 - __bfloat162float(h0);
    float r1 = v1 - __bfloat162float(h1);
    __nv_bfloat16 l0 = __float2bfloat16(r0);
    __nv_bfloat16 l1 = __float2bfloat16(r1);
    hi = (uint32_t)__bfloat16_as_ushort(h0) | ((uint32_t)__bfloat16_as_ushort(h1) << 16);
    lo = (uint32_t)__bfloat16_as_ushort(l0) | ((uint32_t)__bfloat16_as_ushort(l1) << 16);
}

#define MMA_BF16(c, a, b0, b1) \
    asm volatile("mma.sync.aligned.m16n8k16.row.col.f32.bf16.bf16.f32 " \
        "{%0,%1,%2,%3}, {%4,%5,%6,%7}, {%8,%9}, {%0,%1,%2,%3};" \
        : "+f"((c)[0]), "+f"((c)[1]), "+f"((c)[2]), "+f"((c)[3]) \
        : "r"((a)[0]), "r"((a)[1]), "r"((a)[2]), "r"((a)[3]), "r"(b0), "r"(b1))

// ---------------- dtype detection for edge_index --------------------------
__global__ void k_detect(const void* ei, int E, int N) {
    const long long* p = (const long long*)ei;
    int lane = threadIdx.x;
    bool bad = false;
    for (int i = lane; i < 64 && i < E; i += 32) {
        long long v = p[i];
        if (v < 0 || v >= (long long)N) bad = true;
    }
    unsigned m = __ballot_sync(0xffffffffu, bad);
    if (lane == 0) g_is64 = (m == 0);
}

__global__ void k_zero(int N) {
    int i = blockIdx.x * blockDim.x + threadIdx.x;
    if (i < N) g_deg[i] = 0;
}

// convert to int32 + count in-degrees, remember rank within dst segment
__global__ void k_convcount(const void* ei, int E) {
    int e = blockIdx.x * blockDim.x + threadIdx.x;
    if (e >= E) return;
    int s, d;
    if (g_is64) {
        const long long* p = (const long long*)ei;
        s = (int)p[e];
        d = (int)p[(long long)E + e];
    } else {
        const int* p = (const int*)ei;
        s = p[e];
        d = p[E + e];
    }
    g_src[e] = s;
    g_dst[e] = d;
    g_rank[e] = atomicAdd(&g_deg[d], 1);
}

// ---------------- prefix scan over degrees (3 kernels) ---------------------
__global__ void k_scan1(int N) {
    __shared__ int sh[1024];
    int t = threadIdx.x;
    int i = blockIdx.x * 1024 + t;
    int v = (i < N) ? g_deg[i] : 0;
    sh[t] = v;
    __syncthreads();
    for (int off = 1; off < 1024; off <<= 1) {
        int u = (t >= off) ? sh[t - off] : 0;
        __syncthreads();
        sh[t] += u;
        __syncthreads();
    }
    if (i < N) g_incl[i] = sh[t];
    if (t == 1023) g_bsum[blockIdx.x] = sh[t];
}

__global__ void k_scan2(int nblk) {
    __shared__ int sh[1024];
    int t = threadIdx.x;
    int v = (t < nblk) ? g_bsum[t] : 0;
    sh[t] = v;
    __syncthreads();
    for (int off = 1; off < 1024; off <<= 1) {
        int u = (t >= off) ? sh[t - off] : 0;
        __syncthreads();
        sh[t] += u;
        __syncthreads();
    }
    g_boff[t] = sh[t] - v;
}

__global__ void k_scan3(int N) {
    int i = blockIdx.x * blockDim.x + threadIdx.x;
    if (i >= N) return;
    int tot = g_incl[i] + g_boff[i >> 10];
    g_rs[i] = tot - g_deg[i];
    g_re[i] = tot;
}

__global__ void k_scatter(int E) {
    int e = blockIdx.x * blockDim.x + threadIdx.x;
    if (e >= E) return;
    int pos = g_rs[g_dst[e]] + g_rank[e];
    g_csr[pos] = g_src[e];
}

// ---------------- weight prep: transpose + bf16 split into smem image ------
// w1 img: u32[n*68 + p] = pack(W1[2p][n], W1[2p+1][n]) split hi/lo, p<64
// w2 img: u32[n*36 + p] = pack(W2[2p][n], W2[2p+1][n]) split hi/lo, p<32
__global__ void k_prepw(const float* __restrict__ W1, const float* __restrict__ W2) {
    for (int idx = threadIdx.x; idx < W1_U32 + W2_U32; idx += blockDim.x) {
        if (idx < W1_U32) {
            int n = idx / 68, p = idx % 68;
            uint32_t hi = 0, lo = 0;
            if (p < 64) split2(W1[(2 * p) * HID + n], W1[(2 * p + 1) * HID + n], hi, lo);
            g_wimg[idx] = hi;
            g_wimg[W1_U32 + idx] = lo;
        } else {
            int r = idx - W1_U32;
            int n = r / 36, p = r % 36;
            uint32_t hi = 0, lo = 0;
            if (p < 32) split2(W2[(2 * p) * HID + n], W2[(2 * p + 1) * HID + n], hi, lo);
            g_wimg[2 * W1_U32 + r] = hi;
            g_wimg[2 * W1_U32 + W2_U32 + r] = lo;
        }
    }
}

// ---------------- tensor-core MLP (mma.sync bf16 3-term split) -------------
// smem byte offsets (row strides: 272B for K=128 tiles, 144B for K=64 tiles)
#define A1H_OFF   0            // 128 x 272B = 34816
#define A1L_OFF   34816
#define W1TH_OFF  69632        // 64 x 272B = 17408
#define W1TL_OFF  87040
#define W2TH_OFF  104448       // 64 x 144B = 9216
#define W2TL_OFF  113664
#define HTH_OFF   122880       // 128 x 144B = 18432
#define HTL_OFF   141312
#define BIAS_OFF  159744       // b1[64], b2[64] floats = 512B
#define STAGE_OFF 0            // reuse A1 region after GEMMs: 128 x 65 floats
#define SMEM_SZ   160256

__global__ void __launch_bounds__(256) k_mlp_tc(
    const float* __restrict__ x, const float* __restrict__ b1,
    const float* __restrict__ b2, int N)
{
    extern __shared__ char sm[];
    int tid = threadIdx.x;
    int wid = tid >> 5, lane = tid & 31;
    int g = lane >> 2, q = lane & 3;
    int node0 = blockIdx.x * 128;
    int m0 = wid * 16;

    if (tid < 64) {
        ((float*)(sm + BIAS_OFF))[tid] = b1[tid];
        ((float*)(sm + BIAS_OFF))[64 + tid] = b2[tid];
    }
    // weight image copy (contiguous, pre-laid-out)
    {
        const uint4* src = (const uint4*)g_wimg;
        uint4* dst = (uint4*)(sm + W1TH_OFF);
        for (int i = tid; i < WIMG_U32 / 4; i += 256) dst[i] = src[i];
    }
    // x -> A1 hi/lo bf16 tiles (row-major, stride 272B)
    {
        const float2* x2 = (const float2*)x;
        for (int idx = tid; idx < 128 * 64; idx += 256) {
            int r = idx >> 6, p = idx & 63;
            int node = node0 + r;
            float2 v = make_float2(0.f, 0.f);
            if (node < N) v = x2[(size_t)node * 64 + p];
            uint32_t hi, lo;
            split2(v.x, v.y, hi, lo);
            ((uint32_t*)(sm + A1H_OFF))[r * 68 + p] = hi;
            ((uint32_t*)(sm + A1L_OFF))[r * 68 + p] = lo;
        }
    }
    __syncthreads();

    // ---- GEMM1: [128x128] @ W1 -> acc (16x64 per warp) ----
    float acc[8][4];
#pragma unroll
    for (int nt = 0; nt < 8; nt++)
#pragma unroll
        for (int i = 0; i < 4; i++) acc[nt][i] = 0.f;

#pragma unroll
    for (int kk = 0; kk < 8; kk++) {
        uint32_t ah[4], al[4];
        int ab = (m0 + g) * 272 + kk * 32 + q * 4;
        ah[0] = *(const uint32_t*)(sm + A1H_OFF + ab);
        ah[1] = *(const uint32_t*)(sm + A1H_OFF + ab + 8 * 272);
        ah[2] = *(const uint32_t*)(sm + A1H_OFF + ab + 16);
        ah[3] = *(const uint32_t*)(sm + A1H_OFF + ab + 8 * 272 + 16);
        al[0] = *(const uint32_t*)(sm + A1L_OFF + ab);
        al[1] = *(const uint32_t*)(sm + A1L_OFF + ab + 8 * 272);
        al[2] = *(const uint32_t*)(sm + A1L_OFF + ab + 16);
        al[3] = *(const uint32_t*)(sm + A1L_OFF + ab + 8 * 272 + 16);
#pragma unroll
        for (int nt = 0; nt < 8; nt++) {
            int bb = (nt * 8 + g) * 272 + kk * 32 + q * 4;
            uint32_t bh0 = *(const uint32_t*)(sm + W1TH_OFF + bb);
            uint32_t bh1 = *(const uint32_t*)(sm + W1TH_OFF + bb + 16);
            uint32_t bl0 = *(const uint32_t*)(sm + W1TL_OFF + bb);
            uint32_t bl1 = *(const uint32_t*)(sm + W1TL_OFF + bb + 16);
            MMA_BF16(acc[nt], ah, bh0, bh1);
            MMA_BF16(acc[nt], ah, bl0, bl1);
            MMA_BF16(acc[nt], al, bh0, bh1);
        }
    }

    // ---- epilogue1: relu(acc + b1) -> Ht hi/lo (stride 144B) ----
    {
        const float* b1s = (const float*)(sm + BIAS_OFF);
#pragma unroll
        for (int nt = 0; nt < 8; nt++) {
            int c0 = nt * 8 + q * 2;
            float v0 = fmaxf(acc[nt][0] + b1s[c0], 0.f);
            float v1 = fmaxf(acc[nt][1] + b1s[c0 + 1], 0.f);
            float v2 = fmaxf(acc[nt][2] + b1s[c0], 0.f);
            float v3 = fmaxf(acc[nt][3] + b1s[c0 + 1], 0.f);
            uint32_t hi, lo;
            split2(v0, v1, hi, lo);
            int off = (m0 + g) * 144 + c0 * 2;
            *(uint32_t*)(sm + HTH_OFF + off) = hi;
            *(uint32_t*)(sm + HTL_OFF + off) = lo;
            split2(v2, v3, hi, lo);
            off += 8 * 144;
            *(uint32_t*)(sm + HTH_OFF + off) = hi;
            *(uint32_t*)(sm + HTL_OFF + off) = lo;
        }
    }
    __syncthreads();

    // ---- GEMM2: [128x64] @ W2 -> acc ----
#pragma unroll
    for (int nt = 0; nt < 8; nt++)
#pragma unroll
        for (int i = 0; i < 4; i++) acc[nt][i] = 0.f;

#pragma unroll
    for (int kk = 0; kk < 4; kk++) {
        uint32_t ah[4], al[4];
        int ab = (m0 + g) * 144 + kk * 32 + q * 4;
        ah[0] = *(const uint32_t*)(sm + HTH_OFF + ab);
        ah[1] = *(const uint32_t*)(sm + HTH_OFF + ab + 8 * 144);
        ah[2] = *(const uint32_t*)(sm + HTH_OFF + ab + 16);
        ah[3] = *(const uint32_t*)(sm + HTH_OFF + ab + 8 * 144 + 16);
        al[0] = *(const uint32_t*)(sm + HTL_OFF + ab);
        al[1] = *(const uint32_t*)(sm + HTL_OFF + ab + 8 * 144);
        al[2] = *(const uint32_t*)(sm + HTL_OFF + ab + 16);
        al[3] = *(const uint32_t*)(sm + HTL_OFF + ab + 8 * 144 + 16);
#pragma unroll
        for (int nt = 0; nt < 8; nt++) {
            int bb = (nt * 8 + g) * 144 + kk * 32 + q * 4;
            uint32_t bh0 = *(const uint32_t*)(sm + W2TH_OFF + bb);
            uint32_t bh1 = *(const uint32_t*)(sm + W2TH_OFF + bb + 16);
            uint32_t bl0 = *(const uint32_t*)(sm + W2TL_OFF + bb);
            uint32_t bl1 = *(const uint32_t*)(sm + W2TL_OFF + bb + 16);
            MMA_BF16(acc[nt], ah, bh0, bh1);
            MMA_BF16(acc[nt], ah, bl0, bl1);
            MMA_BF16(acc[nt], al, bh0, bh1);
        }
    }

    // ---- epilogue2: h = acc + b2; rnorm per row; stage to smem ----
    {
        const float* b2s = (const float*)(sm + BIAS_OFF) + 64;
        float* stage = (float*)(sm + STAGE_OFF);
        float ssA = 0.f, ssB = 0.f;   // rows m0+g and m0+g+8
#pragma unroll
        for (int nt = 0; nt < 8; nt++) {
            int c0 = nt * 8 + q * 2;
            float h0 = acc[nt][0] + b2s[c0];
            float h1 = acc[nt][1] + b2s[c0 + 1];
            float h2 = acc[nt][2] + b2s[c0];
            float h3 = acc[nt][3] + b2s[c0 + 1];
            ssA += h0 * h0 + h1 * h1;
            ssB += h2 * h2 + h3 * h3;
            stage[(m0 + g) * 65 + c0] = h0;
            stage[(m0 + g) * 65 + c0 + 1] = h1;
            stage[(m0 + g + 8) * 65 + c0] = h2;
            stage[(m0 + g + 8) * 65 + c0 + 1] = h3;
        }
        // quad reduce (lanes 4g..4g+3 share rows)
        ssA += __shfl_xor_sync(0xffffffffu, ssA, 1);
        ssA += __shfl_xor_sync(0xffffffffu, ssA, 2);
        ssB += __shfl_xor_sync(0xffffffffu, ssB, 1);
        ssB += __shfl_xor_sync(0xffffffffu, ssB, 2);
        if (q == 0) {
            int nA = node0 + m0 + g, nB = nA + 8;
            if (nA < N) g_rnorm[nA] = 1.f / fmaxf(sqrtf(ssA), 1e-12f);
            if (nB < N) g_rnorm[nB] = 1.f / fmaxf(sqrtf(ssB), 1e-12f);
        }
    }
    __syncthreads();

    // coalesced store of h
    {
        const float* stage = (const float*)(sm + STAGE_OFF);
        for (int idx = tid; idx < 128 * 64; idx += 256) {
            int r = idx >> 6, c = idx & 63;
            int node = node0 + r;
            if (node < N) g_h[(size_t)node * 64 + c] = stage[r * 65 + c];
        }
    }
}

// ---------------- gather: fixed-shift segment-softmax + agg + classifier ---
__global__ void __launch_bounds__(256) k_gather(
    const float* __restrict__ beta_p, const float* __restrict__ Wc,
    const float* __restrict__ bc, float* __restrict__ out, int N)
{
    int wid = threadIdx.x >> 5;
    int lane = threadIdx.x & 31;
    int n = blockIdx.x * 8 + wid;
    if (n >= N) return;

    float beta = __ldg(beta_p);
    float C = fabsf(beta);     // |e| <= |beta| always -> fixed softmax shift
    const float2* h2 = (const float2*)g_h;
    float2 hd = h2[(size_t)n * 32 + lane];
    float rnd = g_rnorm[n];

    float p = hd.x * hd.x + hd.y * hd.y;
#pragma unroll
    for (int o = 16; o; o >>= 1) p += __shfl_xor_sync(0xffffffffu, p, o);
    float e_self = beta * p * rnd * rnd;
    float w = __expf(e_self - C);
    float s = w;
    float2 acc = make_float2(w * hd.x, w * hd.y);

    int start = g_rs[n], end = g_re[n];
    float brnd = beta * rnd;
    for (int base = start; base < end; base += 32) {
        int k = base + lane;
        int sidx = (k < end) ? g_csr[k] : 0;
        float cj = (k < end) ? brnd * g_rnorm[sidx] : 0.f;
        int cnt = min(32, end - base);
        for (int j0 = 0; j0 < cnt; j0 += 8) {
            float2 hsv[8];
            float cv[8];
#pragma unroll
            for (int jj = 0; jj < 8; jj++) {
                int j = j0 + jj;
                int sj = __shfl_sync(0xffffffffu, sidx, j & 31);
                cv[jj] = __shfl_sync(0xffffffffu, cj, j & 31);
                hsv[jj] = make_float2(0.f, 0.f);
                if (j < cnt) hsv[jj] = h2[(size_t)sj * 32 + lane];
            }
#pragma unroll
            for (int jj = 0; jj < 8; jj++) {
                int j = j0 + jj;
                float d = hd.x * hsv[jj].x + hd.y * hsv[jj].y;
#pragma unroll
                for (int o = 16; o; o >>= 1) d += __shfl_xor_sync(0xffffffffu, d, o);
                if (j < cnt) {
                    float wj = __expf(cv[jj] * d - C);
                    s += wj;
                    acc.x += wj * hsv[jj].x;
                    acc.y += wj * hsv[jj].y;
                }
            }
        }
    }

    float inv = 1.f / (s + 1e-16f);
    float ox = acc.x * inv, oy = acc.y * inv;

    float2 wc0 = ((const float2*)Wc)[lane * 2];
    float2 wc1 = ((const float2*)Wc)[lane * 2 + 1];
    float y0 = ox * wc0.x + oy * wc1.x;
    float y1 = ox * wc0.y + oy * wc1.y;
#pragma unroll
    for (int o = 16; o; o >>= 1) {
        y0 += __shfl_xor_sync(0xffffffffu, y0, o);
        y1 += __shfl_xor_sync(0xffffffffu, y1, o);
    }
    if (lane == 0) {
        out[(size_t)n * 2]     = y0 + bc[0];
        out[(size_t)n * 2 + 1] = y1 + bc[1];
    }
}

// ---------------- launch ---------------------------------------------------
extern "C" void kernel_launch(void* const* d_in, const int* in_sizes, int n_in,
                              void* d_out, int out_size)
{
    const float* x    = (const float*)d_in[0];
    const void*  ei   = d_in[1];
    const float* W1   = (const float*)d_in[2];
    const float* b1   = (const float*)d_in[3];
    const float* W2   = (const float*)d_in[4];
    const float* b2   = (const float*)d_in[5];
    const float* beta = (const float*)d_in[6];
    const float* Wc   = (const float*)d_in[7];
    const float* bc   = (const float*)d_in[8];
    float* y = (float*)d_out;

    int hid    = in_sizes[3];            // 64
    int in_dim = in_sizes[2] / hid;      // 128
    int N      = in_sizes[0] / in_dim;   // 100000
    int E      = in_sizes[1] / 2;        // 1600000

    cudaFuncSetAttribute(k_mlp_tc, cudaFuncAttributeMaxDynamicSharedMemorySize, SMEM_SZ);

    k_detect<<<1, 32>>>(ei, E, N);
    k_zero<<<(N + 255) / 256, 256>>>(N);
    k_convcount<<<(E + 255) / 256, 256>>>(ei, E);

    int nblk = (N + 1023) / 1024;
    k_scan1<<<nblk, 1024>>>(N);
    k_scan2<<<1, 1024>>>(nblk);
    k_scan3<<<(N + 255) / 256, 256>>>(N);
    k_scatter<<<(E + 255) / 256, 256>>>(E);

    k_prepw<<<1, 256>>>(W1, W2);
    k_mlp_tc<<<(N + 127) / 128, 256, SMEM_SZ>>>(x, b1, b2, N);
    k_gather<<<(N + 7) / 8, 256>>>(beta, Wc, bc, y, N);
}